// round 13
// baseline (speedup 1.0000x reference)
#include <cuda_runtime.h>
#include <math.h>
#include <stdint.h>

#define BB 2
#define NN 4096
#define HH 16
#define DD 64
#define CC 1024
#define BN (BB*NN)            // 8192 tokens
#define TAU 0.006f
#define FTOK 32               // flagged tokens per fix block
#define CH 64                 // codes per mma chunk (double-buffered)
#define FSPLIT 4              // code-range splits in fix kernel

typedef unsigned long long u64;

// Scratch (no cudaMalloc allowed).
__device__ __align__(16) float g_k  [HH*CC*DD];   // exact projected keys
__device__ __align__(16) float g_ktf[HH*CC*DD];   // tf32-rounded keys
__device__ __align__(16) float g_v  [HH*CC*DD];   // projected values
__device__ int g_hist[HH*CC];
__device__ int g_idx[HH*BN];                      // argmax; bit16 = flagged
__device__ u64 g_fixkey[HH*BN];                   // merged exact (score, code) key
__device__ int g_cnt_h[HH];
__device__ int g_list_h[HH][BN];                  // flagged tokens per head

__device__ __forceinline__ float tf32r(float f) {
    asm("cvt.rna.tf32.f32 %0, %1;" : "=f"(f) : "f"(f));
    return f;
}

__device__ __forceinline__ void mma_tf32(float c[4], const uint32_t a[4],
                                         uint32_t b0, uint32_t b1) {
    asm volatile(
        "mma.sync.aligned.m16n8k8.row.col.f32.tf32.tf32.f32 "
        "{%0,%1,%2,%3}, {%4,%5,%6,%7}, {%8,%9}, {%0,%1,%2,%3};"
        : "+f"(c[0]), "+f"(c[1]), "+f"(c[2]), "+f"(c[3])
        : "r"(a[0]), "r"(a[1]), "r"(a[2]), "r"(a[3]), "r"(b0), "r"(b1));
}

__device__ __forceinline__ uint32_t smem_u32(const void* p) {
    return (uint32_t)__cvta_generic_to_shared(p);
}
__device__ __forceinline__ void cpasync16(uint32_t dst, const void* src) {
    asm volatile("cp.async.cg.shared.global [%0], [%1], 16;"
                 :: "r"(dst), "l"(src));
}
__device__ __forceinline__ void cpasync_commit() {
    asm volatile("cp.async.commit_group;");
}
template<int N>
__device__ __forceinline__ void cpasync_wait() {
    asm volatile("cp.async.wait_group %0;" :: "n"(N));
}

// Order-preserving float -> u32 (monotone: a > b  <=>  enc(a) > enc(b)).
__device__ __forceinline__ uint32_t ordf(float f) {
    uint32_t b = __float_as_uint(f);
    return (b & 0x80000000u) ? ~b : (b | 0x80000000u);
}

// Pairwise top-2 update: two adjacent codes (code0, code0+1), first-max ties.
__device__ __forceinline__ void upd2(float& b, float& s, int& bi,
                                     float v0, float v1, int code0) {
    float mx = fmaxf(v0, v1);
    float mn = fminf(v0, v1);
    int idx  = code0 + ((v1 > v0) ? 1 : 0);
    if (mx > b) { s = fmaxf(b, mn); b = mx; bi = idx; }
    else        { s = fmaxf(s, mx); }
}

// ---------------------------------------------------------------------------
// Phase A: k = cb @ wk (exact + tf32 copy), v = cb @ wv.
// Block (0,0) also zeroes hist/counters (consumed only by later kernels).
// ---------------------------------------------------------------------------
__global__ void kv_kernel(const float* __restrict__ cb,
                          const float* __restrict__ wk,
                          const float* __restrict__ wv) {
    int h  = blockIdx.x;
    int c0 = blockIdx.y * 16;
    int tid = threadIdx.x;

    if (blockIdx.x == 0 && blockIdx.y == 0) {
        for (int i = tid; i < HH*CC; i += 256) g_hist[i] = 0;
        if (tid < HH) g_cnt_h[tid] = 0;
    }

    __shared__ float s_wk[DD*DD];
    __shared__ float s_wv[DD*DD];
    __shared__ float s_cb[16*DD];
    for (int i = tid; i < DD*DD; i += 256) {
        s_wk[i] = wk[h*DD*DD + i];
        s_wv[i] = wv[h*DD*DD + i];
    }
    for (int i = tid; i < 16*DD; i += 256)
        s_cb[i] = cb[(size_t)h*CC*DD + (size_t)c0*DD + i];
    __syncthreads();
    int d  = tid & 63;
    int cl = tid >> 6;
    for (int cc = cl; cc < 16; cc += 4) {
        float ak = 0.f, av = 0.f;
        #pragma unroll
        for (int e = 0; e < DD; e++) {
            float cbe = s_cb[cc*DD + e];
            ak = fmaf(cbe, s_wk[e*DD + d], ak);
            av = fmaf(cbe, s_wv[e*DD + d], av);
        }
        size_t off = ((size_t)h*CC + (c0 + cc))*DD + d;
        g_k[off]   = ak;
        g_ktf[off] = tf32r(ak);
        g_v[off]   = av;
    }
}

// ---------------------------------------------------------------------------
// Phase B: TF32 mma logits + top-2 tracking.
// grid (BN/128, HH), block 128 (4 warps). Warp owns 32 tokens (2 M-tiles).
// 64-code chunks double-buffered via cp.async.
// ---------------------------------------------------------------------------
__global__ void __launch_bounds__(128)
mma_argmax_kernel(const float* __restrict__ x) {
    int h    = blockIdx.y;
    int tblk = blockIdx.x * 128;
    int tid  = threadIdx.x, warp = tid >> 5, lane = tid & 31;
    int g    = lane >> 2,   tg   = lane & 3;

    __shared__ float k_s[2][CH * 68];

    uint32_t a[2][8][4];
    {
        int r0 = tblk + warp*32 + g;
        const float* xb = x + (size_t)r0 * (HH*DD) + h*DD;
        #pragma unroll
        for (int m = 0; m < 2; m++) {
            #pragma unroll
            for (int ks = 0; ks < 8; ks++) {
                const float* p0 = xb + (size_t)(m*16    ) * (HH*DD) + ks*8 + tg;
                const float* p1 = xb + (size_t)(m*16 + 8) * (HH*DD) + ks*8 + tg;
                a[m][ks][0] = __float_as_uint(tf32r(p0[0] * 0.125f));
                a[m][ks][1] = __float_as_uint(tf32r(p1[0] * 0.125f));
                a[m][ks][2] = __float_as_uint(tf32r(p0[4] * 0.125f));
                a[m][ks][3] = __float_as_uint(tf32r(p1[4] * 0.125f));
            }
        }
    }

    float best[4], sec[4]; int bidx[4];
    #pragma unroll
    for (int s = 0; s < 4; s++) { best[s] = -INFINITY; sec[s] = -INFINITY; bidx[s] = 0; }

    const float* kbase = g_ktf + (size_t)h*CC*DD;

    {
        for (int i = tid; i < CH*16; i += 128) {
            int row = i >> 4, c4 = (i & 15) * 4;
            cpasync16(smem_u32(&k_s[0][row*68 + c4]), kbase + row*DD + c4);
        }
        cpasync_commit();
    }

    for (int c = 0; c < CC/CH; c++) {
        int cur = c & 1;
        if (c + 1 < CC/CH) {
            int nxt = (c + 1) & 1;
            const float* kc = kbase + (size_t)(c + 1)*CH*DD;
            for (int i = tid; i < CH*16; i += 128) {
                int row = i >> 4, c4 = (i & 15) * 4;
                cpasync16(smem_u32(&k_s[nxt][row*68 + c4]), kc + row*DD + c4);
            }
            cpasync_commit();
            cpasync_wait<1>();
        } else {
            cpasync_wait<0>();
        }
        __syncthreads();

        int jt = c * CH;
        #pragma unroll 1
        for (int nt = 0; nt < CH/8; nt++) {
            float c0[4] = {0,0,0,0}, c1[4] = {0,0,0,0};
            const float* kb = &k_s[cur][(nt*8 + g)*68];
            #pragma unroll
            for (int ks = 0; ks < 8; ks++) {
                uint32_t v0 = __float_as_uint(kb[ks*8 + tg]);
                uint32_t v1 = __float_as_uint(kb[ks*8 + tg + 4]);
                mma_tf32(c0, a[0][ks], v0, v1);
                mma_tf32(c1, a[1][ks], v0, v1);
            }
            int code0 = jt + nt*8 + 2*tg;
            upd2(best[0], sec[0], bidx[0], c0[0], c0[1], code0);
            upd2(best[1], sec[1], bidx[1], c0[2], c0[3], code0);
            upd2(best[2], sec[2], bidx[2], c1[0], c1[1], code0);
            upd2(best[3], sec[3], bidx[3], c1[2], c1[3], code0);
        }
        __syncthreads();
    }

    #pragma unroll
    for (int off = 1; off < 4; off <<= 1) {
        #pragma unroll
        for (int s = 0; s < 4; s++) {
            float ob = __shfl_xor_sync(0xffffffffu, best[s], off);
            float os = __shfl_xor_sync(0xffffffffu, sec[s],  off);
            int   oi = __shfl_xor_sync(0xffffffffu, bidx[s], off);
            float ns = fmaxf(fmaxf(sec[s], os), fminf(best[s], ob));
            bool take = (ob > best[s]) || (ob == best[s] && oi < bidx[s]);
            if (take) { best[s] = ob; bidx[s] = oi; }
            sec[s] = ns;
        }
    }

    if (tg == 0) {
        #pragma unroll
        for (int s = 0; s < 4; s++) {
            int m = s >> 1, r8 = (s & 1) * 8;
            int tok = tblk + warp*32 + m*16 + g + r8;
            int e = h*BN + tok;
            if (best[s] - sec[s] < TAU) {
                g_idx[e] = bidx[s] | 0x10000;     // flagged
                g_fixkey[e] = 0ull;
                int pos = atomicAdd(&g_cnt_h[h], 1);
                g_list_h[h][pos] = tok;
            } else {
                g_idx[e] = bidx[s];
            }
        }
    }
}

// ---------------------------------------------------------------------------
// Phase B2: exact fp32 rescue — grid (H, BN/FTOK, FSPLIT), block 512.
// 16 threads per token; each z-block covers CC/FSPLIT codes (2 chunks of 128).
// Partial argmaxes merged via atomicMax on (ordf(score), 1023-code) key.
// Exact 4-way accumulation order.
// ---------------------------------------------------------------------------
__global__ void __launch_bounds__(512)
fix_kernel(const float* __restrict__ x) {
    int h    = blockIdx.x;
    int base = blockIdx.y * FTOK;
    int zc   = blockIdx.z;
    int cnt  = g_cnt_h[h];
    if (base >= cnt) return;

    int tid   = threadIdx.x;
    int tslot = tid >> 4, part = tid & 15;   // 32 tokens x 16 parts
    int ntok  = cnt - base; if (ntok > FTOK) ntok = FTOK;
    bool act  = (tslot < ntok);
    int tok   = g_list_h[h][base + (act ? tslot : 0)];

    float q[64];
    {
        const float4* xq = (const float4*)(x + (size_t)tok*(HH*DD) + h*DD);
        #pragma unroll
        for (int i = 0; i < 16; i++) {
            float4 v = xq[i];
            q[4*i]   = v.x * 0.125f; q[4*i+1] = v.y * 0.125f;
            q[4*i+2] = v.z * 0.125f; q[4*i+3] = v.w * 0.125f;
        }
    }

    __shared__ float ks[128 * 68];

    float best = -INFINITY; int bi = 0;

    for (int c = 0; c < CC/(128*FSPLIT); c++) {
        int jt = (zc * (CC/FSPLIT)) + c * 128;
        __syncthreads();
        for (int i = tid; i < 128*16; i += 512) {
            int row = i >> 4, c4 = (i & 15) * 4;
            float4 v = *(const float4*)(g_k + ((size_t)h*CC + jt + row)*DD + c4);
            *(float4*)&ks[row*68 + c4] = v;
        }
        __syncthreads();

        #pragma unroll 2
        for (int cc8 = 0; cc8 < 8; cc8++) {
            int cl = cc8*16 + part;
            const float4* kr = (const float4*)&ks[cl*68];
            float a0=0.f, a1=0.f, a2=0.f, a3=0.f;
            #pragma unroll
            for (int d4 = 0; d4 < 16; d4++) {
                float4 kv = kr[d4];
                a0 = fmaf(q[4*d4+0], kv.x, a0);
                a1 = fmaf(q[4*d4+1], kv.y, a1);
                a2 = fmaf(q[4*d4+2], kv.z, a2);
                a3 = fmaf(q[4*d4+3], kv.w, a3);
            }
            float acc = (a0 + a1) + (a2 + a3);
            int code = jt + cl;
            if (acc > best) { best = acc; bi = code; }
        }
    }

    if (act) {
        u64 key = ((u64)ordf(best) << 32) | (u64)(uint32_t)(1023 - bi);
        atomicMax(&g_fixkey[h*BN + tok], key);
    }
}

// ---------------------------------------------------------------------------
// Phase C: gather v rows, write indices, histogram. 8 threads per (t,h).
// Flagged tokens decode the exact argmax from g_fixkey.
// ---------------------------------------------------------------------------
__global__ void __launch_bounds__(256)
gather_kernel(float* __restrict__ out_base) {
    int gid = blockIdx.x * 256 + threadIdx.x;
    int s = gid & 7;
    int h = (gid >> 3) & 15;
    int t = gid >> 7;
    int e = h*BN + t;
    int raw = g_idx[e];
    int idx;
    if (raw & 0x10000) idx = 1023 - (int)(g_fixkey[e] & 0xFFFFu);
    else               idx = raw & 1023;
    const float4* vr = (const float4*)(g_v + ((size_t)h*CC + idx)*DD + s*8);
    float4* orow = (float4*)(out_base + (size_t)t*(HH*DD) + h*DD + s*8);
    orow[0] = vr[0]; orow[1] = vr[1];
    if (s == 0) {
        int b  = t >> 12;
        int ii = t & (NN - 1);
        float* idx_out = out_base + (size_t)BN*HH*DD;
        idx_out[((size_t)b*HH + h)*NN + ii] = (float)idx;
        atomicAdd(&g_hist[h*CC + idx], 1);
    }
}

// ---------------------------------------------------------------------------
// Phase D: perplexity per head.
// ---------------------------------------------------------------------------
__global__ void perp_kernel(float* __restrict__ out_base) {
    int h = blockIdx.x;
    __shared__ float red[256];
    float s = 0.f;
    const float inv = 1.0f / (float)BN;
    for (int c = threadIdx.x; c < CC; c += 256) {
        float m = (float)g_hist[h*CC + c] * inv;
        s += m * logf(m + 1e-10f);
    }
    red[threadIdx.x] = s;
    __syncthreads();
    for (int o = 128; o > 0; o >>= 1) {
        if (threadIdx.x < o) red[threadIdx.x] += red[threadIdx.x + o];
        __syncthreads();
    }
    if (threadIdx.x == 0) {
        size_t perp_off = (size_t)BN*HH*DD + (size_t)BB*HH*NN;
        out_base[perp_off + h] = expf(-red[0]);
    }
}

// ---------------------------------------------------------------------------
extern "C" void kernel_launch(void* const* d_in, const int* in_sizes, int n_in,
                              void* d_out, int out_size) {
    const float* x  = (const float*)d_in[0];   // (B, N, H*D)
    const float* cb = (const float*)d_in[1];   // (H, C, D)
    const float* wk = (const float*)d_in[2];   // (H, D, D)
    const float* wv = (const float*)d_in[3];   // (H, D, D)
    float* out = (float*)d_out;

    dim3 gkv(HH, CC/16);
    kv_kernel<<<gkv, 256>>>(cb, wk, wv);

    dim3 gm(BN/128, HH);
    mma_argmax_kernel<<<gm, 128>>>(x);

    dim3 gf(HH, BN/FTOK, FSPLIT);              // blocks past cnt exit instantly
    fix_kernel<<<gf, 512>>>(x);

    gather_kernel<<<(BN*HH*8)/256, 256>>>(out);

    perp_kernel<<<HH, 256>>>(out);
}

// round 14
// speedup vs baseline: 1.0037x; 1.0037x over previous
#include <cuda_runtime.h>
#include <math.h>
#include <stdint.h>

#define BB 2
#define NN 4096
#define HH 16
#define DD 64
#define CC 1024
#define BN (BB*NN)            // 8192 tokens
#define TAU 0.006f
#define FTOK 32               // flagged tokens per fix block
#define CH 64                 // codes per mma chunk (double-buffered)
#define FSPLIT 4              // code-range splits in fix kernel

typedef unsigned long long u64;

// Scratch (no cudaMalloc allowed).
__device__ __align__(16) float g_k  [HH*CC*DD];   // exact projected keys
__device__ __align__(16) float g_ktf[HH*CC*DD];   // tf32-rounded keys
__device__ __align__(16) float g_v  [HH*CC*DD];   // projected values
__device__ int g_hist[HH*CC];
__device__ int g_idx[HH*BN];                      // argmax; bit16 = flagged
__device__ u64 g_fixkey[HH*BN];                   // merged exact (score, code) key
__device__ int g_cnt_h[HH];
__device__ int g_list_h[HH][BN];                  // flagged tokens per head

__device__ __forceinline__ float tf32r(float f) {
    asm("cvt.rna.tf32.f32 %0, %1;" : "=f"(f) : "f"(f));
    return f;
}

__device__ __forceinline__ void mma_tf32(float c[4], const uint32_t a[4],
                                         uint32_t b0, uint32_t b1) {
    asm volatile(
        "mma.sync.aligned.m16n8k8.row.col.f32.tf32.tf32.f32 "
        "{%0,%1,%2,%3}, {%4,%5,%6,%7}, {%8,%9}, {%0,%1,%2,%3};"
        : "+f"(c[0]), "+f"(c[1]), "+f"(c[2]), "+f"(c[3])
        : "r"(a[0]), "r"(a[1]), "r"(a[2]), "r"(a[3]), "r"(b0), "r"(b1));
}

__device__ __forceinline__ uint32_t smem_u32(const void* p) {
    return (uint32_t)__cvta_generic_to_shared(p);
}
__device__ __forceinline__ void cpasync16(uint32_t dst, const void* src) {
    asm volatile("cp.async.cg.shared.global [%0], [%1], 16;"
                 :: "r"(dst), "l"(src));
}
__device__ __forceinline__ void cpasync_commit() {
    asm volatile("cp.async.commit_group;");
}
template<int N>
__device__ __forceinline__ void cpasync_wait() {
    asm volatile("cp.async.wait_group %0;" :: "n"(N));
}

// Order-preserving float -> u32 (monotone: a > b  <=>  enc(a) > enc(b)).
__device__ __forceinline__ uint32_t ordf(float f) {
    uint32_t b = __float_as_uint(f);
    return (b & 0x80000000u) ? ~b : (b | 0x80000000u);
}

// Pairwise top-2 update: two adjacent codes (code0, code0+1), first-max ties.
__device__ __forceinline__ void upd2(float& b, float& s, int& bi,
                                     float v0, float v1, int code0) {
    float mx = fmaxf(v0, v1);
    float mn = fminf(v0, v1);
    int idx  = code0 + ((v1 > v0) ? 1 : 0);
    if (mx > b) { s = fmaxf(b, mn); b = mx; bi = idx; }
    else        { s = fmaxf(s, mx); }
}

// ---------------------------------------------------------------------------
// Phase A: k = cb @ wk (exact + tf32 copy), v = cb @ wv.
// Block (0,0) also zeroes hist/counters (consumed only by later kernels).
// ---------------------------------------------------------------------------
__global__ void kv_kernel(const float* __restrict__ cb,
                          const float* __restrict__ wk,
                          const float* __restrict__ wv) {
    int h  = blockIdx.x;
    int c0 = blockIdx.y * 16;
    int tid = threadIdx.x;

    if (blockIdx.x == 0 && blockIdx.y == 0) {
        for (int i = tid; i < HH*CC; i += 256) g_hist[i] = 0;
        if (tid < HH) g_cnt_h[tid] = 0;
    }

    __shared__ float s_wk[DD*DD];
    __shared__ float s_wv[DD*DD];
    __shared__ float s_cb[16*DD];
    for (int i = tid; i < DD*DD; i += 256) {
        s_wk[i] = wk[h*DD*DD + i];
        s_wv[i] = wv[h*DD*DD + i];
    }
    for (int i = tid; i < 16*DD; i += 256)
        s_cb[i] = cb[(size_t)h*CC*DD + (size_t)c0*DD + i];
    __syncthreads();
    int d  = tid & 63;
    int cl = tid >> 6;
    for (int cc = cl; cc < 16; cc += 4) {
        float ak = 0.f, av = 0.f;
        #pragma unroll
        for (int e = 0; e < DD; e++) {
            float cbe = s_cb[cc*DD + e];
            ak = fmaf(cbe, s_wk[e*DD + d], ak);
            av = fmaf(cbe, s_wv[e*DD + d], av);
        }
        size_t off = ((size_t)h*CC + (c0 + cc))*DD + d;
        g_k[off]   = ak;
        g_ktf[off] = tf32r(ak);
        g_v[off]   = av;
    }
}

// ---------------------------------------------------------------------------
// Phase B: TF32 mma logits + top-2 tracking.
// grid (BN/128, HH), block 128 (4 warps). Warp owns 32 tokens (2 M-tiles).
// 64-code chunks double-buffered via cp.async.
// ---------------------------------------------------------------------------
__global__ void __launch_bounds__(128)
mma_argmax_kernel(const float* __restrict__ x) {
    int h    = blockIdx.y;
    int tblk = blockIdx.x * 128;
    int tid  = threadIdx.x, warp = tid >> 5, lane = tid & 31;
    int g    = lane >> 2,   tg   = lane & 3;

    __shared__ float k_s[2][CH * 68];

    uint32_t a[2][8][4];
    {
        int r0 = tblk + warp*32 + g;
        const float* xb = x + (size_t)r0 * (HH*DD) + h*DD;
        #pragma unroll
        for (int m = 0; m < 2; m++) {
            #pragma unroll
            for (int ks = 0; ks < 8; ks++) {
                const float* p0 = xb + (size_t)(m*16    ) * (HH*DD) + ks*8 + tg;
                const float* p1 = xb + (size_t)(m*16 + 8) * (HH*DD) + ks*8 + tg;
                a[m][ks][0] = __float_as_uint(tf32r(p0[0] * 0.125f));
                a[m][ks][1] = __float_as_uint(tf32r(p1[0] * 0.125f));
                a[m][ks][2] = __float_as_uint(tf32r(p0[4] * 0.125f));
                a[m][ks][3] = __float_as_uint(tf32r(p1[4] * 0.125f));
            }
        }
    }

    float best[4], sec[4]; int bidx[4];
    #pragma unroll
    for (int s = 0; s < 4; s++) { best[s] = -INFINITY; sec[s] = -INFINITY; bidx[s] = 0; }

    const float* kbase = g_ktf + (size_t)h*CC*DD;

    {
        for (int i = tid; i < CH*16; i += 128) {
            int row = i >> 4, c4 = (i & 15) * 4;
            cpasync16(smem_u32(&k_s[0][row*68 + c4]), kbase + row*DD + c4);
        }
        cpasync_commit();
    }

    for (int c = 0; c < CC/CH; c++) {
        int cur = c & 1;
        if (c + 1 < CC/CH) {
            int nxt = (c + 1) & 1;
            const float* kc = kbase + (size_t)(c + 1)*CH*DD;
            for (int i = tid; i < CH*16; i += 128) {
                int row = i >> 4, c4 = (i & 15) * 4;
                cpasync16(smem_u32(&k_s[nxt][row*68 + c4]), kc + row*DD + c4);
            }
            cpasync_commit();
            cpasync_wait<1>();
        } else {
            cpasync_wait<0>();
        }
        __syncthreads();

        int jt = c * CH;
        #pragma unroll 1
        for (int nt = 0; nt < CH/8; nt++) {
            float c0[4] = {0,0,0,0}, c1[4] = {0,0,0,0};
            const float* kb = &k_s[cur][(nt*8 + g)*68];
            #pragma unroll
            for (int ks = 0; ks < 8; ks++) {
                uint32_t v0 = __float_as_uint(kb[ks*8 + tg]);
                uint32_t v1 = __float_as_uint(kb[ks*8 + tg + 4]);
                mma_tf32(c0, a[0][ks], v0, v1);
                mma_tf32(c1, a[1][ks], v0, v1);
            }
            int code0 = jt + nt*8 + 2*tg;
            upd2(best[0], sec[0], bidx[0], c0[0], c0[1], code0);
            upd2(best[1], sec[1], bidx[1], c0[2], c0[3], code0);
            upd2(best[2], sec[2], bidx[2], c1[0], c1[1], code0);
            upd2(best[3], sec[3], bidx[3], c1[2], c1[3], code0);
        }
        __syncthreads();
    }

    #pragma unroll
    for (int off = 1; off < 4; off <<= 1) {
        #pragma unroll
        for (int s = 0; s < 4; s++) {
            float ob = __shfl_xor_sync(0xffffffffu, best[s], off);
            float os = __shfl_xor_sync(0xffffffffu, sec[s],  off);
            int   oi = __shfl_xor_sync(0xffffffffu, bidx[s], off);
            float ns = fmaxf(fmaxf(sec[s], os), fminf(best[s], ob));
            bool take = (ob > best[s]) || (ob == best[s] && oi < bidx[s]);
            if (take) { best[s] = ob; bidx[s] = oi; }
            sec[s] = ns;
        }
    }

    if (tg == 0) {
        #pragma unroll
        for (int s = 0; s < 4; s++) {
            int m = s >> 1, r8 = (s & 1) * 8;
            int tok = tblk + warp*32 + m*16 + g + r8;
            int e = h*BN + tok;
            if (best[s] - sec[s] < TAU) {
                g_idx[e] = bidx[s] | 0x10000;     // flagged
                g_fixkey[e] = 0ull;
                int pos = atomicAdd(&g_cnt_h[h], 1);
                g_list_h[h][pos] = tok;
            } else {
                g_idx[e] = bidx[s];
            }
        }
    }
}

// ---------------------------------------------------------------------------
// Phase B2: exact fp32 rescue — grid (H, BN/FTOK, FSPLIT), block 512.
// 16 threads per token; each z-block covers CC/FSPLIT codes (2 chunks of 128).
// Partial argmaxes merged via atomicMax on (ordf(score), 1023-code) key.
// Exact 4-way accumulation order.
// ---------------------------------------------------------------------------
__global__ void __launch_bounds__(512)
fix_kernel(const float* __restrict__ x) {
    int h    = blockIdx.x;
    int base = blockIdx.y * FTOK;
    int zc   = blockIdx.z;
    int cnt  = g_cnt_h[h];
    if (base >= cnt) return;

    int tid   = threadIdx.x;
    int tslot = tid >> 4, part = tid & 15;   // 32 tokens x 16 parts
    int ntok  = cnt - base; if (ntok > FTOK) ntok = FTOK;
    bool act  = (tslot < ntok);
    int tok   = g_list_h[h][base + (act ? tslot : 0)];

    float q[64];
    {
        const float4* xq = (const float4*)(x + (size_t)tok*(HH*DD) + h*DD);
        #pragma unroll
        for (int i = 0; i < 16; i++) {
            float4 v = xq[i];
            q[4*i]   = v.x * 0.125f; q[4*i+1] = v.y * 0.125f;
            q[4*i+2] = v.z * 0.125f; q[4*i+3] = v.w * 0.125f;
        }
    }

    __shared__ float ks[128 * 68];

    float best = -INFINITY; int bi = 0;

    for (int c = 0; c < CC/(128*FSPLIT); c++) {
        int jt = (zc * (CC/FSPLIT)) + c * 128;
        __syncthreads();
        for (int i = tid; i < 128*16; i += 512) {
            int row = i >> 4, c4 = (i & 15) * 4;
            float4 v = *(const float4*)(g_k + ((size_t)h*CC + jt + row)*DD + c4);
            *(float4*)&ks[row*68 + c4] = v;
        }
        __syncthreads();

        #pragma unroll 2
        for (int cc8 = 0; cc8 < 8; cc8++) {
            int cl = cc8*16 + part;
            const float4* kr = (const float4*)&ks[cl*68];
            float a0=0.f, a1=0.f, a2=0.f, a3=0.f;
            #pragma unroll
            for (int d4 = 0; d4 < 16; d4++) {
                float4 kv = kr[d4];
                a0 = fmaf(q[4*d4+0], kv.x, a0);
                a1 = fmaf(q[4*d4+1], kv.y, a1);
                a2 = fmaf(q[4*d4+2], kv.z, a2);
                a3 = fmaf(q[4*d4+3], kv.w, a3);
            }
            float acc = (a0 + a1) + (a2 + a3);
            int code = jt + cl;
            if (acc > best) { best = acc; bi = code; }
        }
    }

    if (act) {
        u64 key = ((u64)ordf(best) << 32) | (u64)(uint32_t)(1023 - bi);
        atomicMax(&g_fixkey[h*BN + tok], key);
    }
}

// ---------------------------------------------------------------------------
// Phase C: gather v rows, write indices, histogram. 8 threads per (t,h).
// Flagged tokens decode the exact argmax from g_fixkey.
// ---------------------------------------------------------------------------
__global__ void __launch_bounds__(256)
gather_kernel(float* __restrict__ out_base) {
    int gid = blockIdx.x * 256 + threadIdx.x;
    int s = gid & 7;
    int h = (gid >> 3) & 15;
    int t = gid >> 7;
    int e = h*BN + t;
    int raw = g_idx[e];
    int idx;
    if (raw & 0x10000) idx = 1023 - (int)(g_fixkey[e] & 0xFFFFu);
    else               idx = raw & 1023;
    const float4* vr = (const float4*)(g_v + ((size_t)h*CC + idx)*DD + s*8);
    float4* orow = (float4*)(out_base + (size_t)t*(HH*DD) + h*DD + s*8);
    orow[0] = vr[0]; orow[1] = vr[1];
    if (s == 0) {
        int b  = t >> 12;
        int ii = t & (NN - 1);
        float* idx_out = out_base + (size_t)BN*HH*DD;
        idx_out[((size_t)b*HH + h)*NN + ii] = (float)idx;
        atomicAdd(&g_hist[h*CC + idx], 1);
    }
}

// ---------------------------------------------------------------------------
// Phase D: perplexity per head.
// ---------------------------------------------------------------------------
__global__ void perp_kernel(float* __restrict__ out_base) {
    int h = blockIdx.x;
    __shared__ float red[256];
    float s = 0.f;
    const float inv = 1.0f / (float)BN;
    for (int c = threadIdx.x; c < CC; c += 256) {
        float m = (float)g_hist[h*CC + c] * inv;
        s += m * logf(m + 1e-10f);
    }
    red[threadIdx.x] = s;
    __syncthreads();
    for (int o = 128; o > 0; o >>= 1) {
        if (threadIdx.x < o) red[threadIdx.x] += red[threadIdx.x + o];
        __syncthreads();
    }
    if (threadIdx.x == 0) {
        size_t perp_off = (size_t)BN*HH*DD + (size_t)BB*HH*NN;
        out_base[perp_off + h] = expf(-red[0]);
    }
}

// ---------------------------------------------------------------------------
extern "C" void kernel_launch(void* const* d_in, const int* in_sizes, int n_in,
                              void* d_out, int out_size) {
    const float* x  = (const float*)d_in[0];   // (B, N, H*D)
    const float* cb = (const float*)d_in[1];   // (H, C, D)
    const float* wk = (const float*)d_in[2];   // (H, D, D)
    const float* wv = (const float*)d_in[3];   // (H, D, D)
    float* out = (float*)d_out;

    dim3 gkv(HH, CC/16);
    kv_kernel<<<gkv, 256>>>(cb, wk, wv);

    dim3 gm(BN/128, HH);
    mma_argmax_kernel<<<gm, 128>>>(x);

    dim3 gf(HH, BN/FTOK, FSPLIT);              // blocks past cnt exit instantly
    fix_kernel<<<gf, 512>>>(x);

    gather_kernel<<<(BN*HH*8)/256, 256>>>(out);

    perp_kernel<<<HH, 256>>>(out);
}

// round 15
// speedup vs baseline: 1.0041x; 1.0004x over previous
#include <cuda_runtime.h>
#include <math.h>
#include <stdint.h>

#define BB 2
#define NN 4096
#define HH 16
#define DD 64
#define CC 1024
#define BN (BB*NN)            // 8192 tokens
#define TAU 0.006f
#define FTOK 32               // flagged tokens per fix block
#define CH 64                 // codes per mma chunk (double-buffered)
#define FSPLIT 4              // code-range splits in fix kernel

typedef unsigned long long u64;

// Scratch (no cudaMalloc allowed).
__device__ __align__(16) float g_k  [HH*CC*DD];   // exact projected keys
__device__ __align__(16) float g_ktf[HH*CC*DD];   // tf32-rounded keys
__device__ __align__(16) float g_v  [HH*CC*DD];   // projected values
__device__ int g_hist[HH*CC];
__device__ int g_idx[HH*BN];                      // argmax; bit16 = flagged
__device__ u64 g_fixkey[HH*BN];                   // merged exact (score, code) key
__device__ int g_cnt_h[HH];
__device__ int g_list_h[HH][BN];                  // flagged tokens per head

__device__ __forceinline__ float tf32r(float f) {
    asm("cvt.rna.tf32.f32 %0, %1;" : "=f"(f) : "f"(f));
    return f;
}

__device__ __forceinline__ void mma_tf32(float c[4], const uint32_t a[4],
                                         uint32_t b0, uint32_t b1) {
    asm volatile(
        "mma.sync.aligned.m16n8k8.row.col.f32.tf32.tf32.f32 "
        "{%0,%1,%2,%3}, {%4,%5,%6,%7}, {%8,%9}, {%0,%1,%2,%3};"
        : "+f"(c[0]), "+f"(c[1]), "+f"(c[2]), "+f"(c[3])
        : "r"(a[0]), "r"(a[1]), "r"(a[2]), "r"(a[3]), "r"(b0), "r"(b1));
}

__device__ __forceinline__ uint32_t smem_u32(const void* p) {
    return (uint32_t)__cvta_generic_to_shared(p);
}
__device__ __forceinline__ void cpasync16(uint32_t dst, const void* src) {
    asm volatile("cp.async.cg.shared.global [%0], [%1], 16;"
                 :: "r"(dst), "l"(src));
}
__device__ __forceinline__ void cpasync_commit() {
    asm volatile("cp.async.commit_group;");
}
template<int N>
__device__ __forceinline__ void cpasync_wait() {
    asm volatile("cp.async.wait_group %0;" :: "n"(N));
}

// Order-preserving float -> u32 (monotone: a > b  <=>  enc(a) > enc(b)).
__device__ __forceinline__ uint32_t ordf(float f) {
    uint32_t b = __float_as_uint(f);
    return (b & 0x80000000u) ? ~b : (b | 0x80000000u);
}

// Pairwise top-2 update: two adjacent codes (code0, code0+1), first-max ties.
__device__ __forceinline__ void upd2(float& b, float& s, int& bi,
                                     float v0, float v1, int code0) {
    float mx = fmaxf(v0, v1);
    float mn = fminf(v0, v1);
    int idx  = code0 + ((v1 > v0) ? 1 : 0);
    if (mx > b) { s = fmaxf(b, mn); b = mx; bi = idx; }
    else        { s = fmaxf(s, mx); }
}

// ---------------------------------------------------------------------------
// Phase A: k = cb @ wk (exact + tf32 copy), v = cb @ wv.
// Block (0,0) also zeroes hist/counters (consumed only by later kernels).
// ---------------------------------------------------------------------------
__global__ void kv_kernel(const float* __restrict__ cb,
                          const float* __restrict__ wk,
                          const float* __restrict__ wv) {
    int h  = blockIdx.x;
    int c0 = blockIdx.y * 16;
    int tid = threadIdx.x;

    if (blockIdx.x == 0 && blockIdx.y == 0) {
        for (int i = tid; i < HH*CC; i += 256) g_hist[i] = 0;
        if (tid < HH) g_cnt_h[tid] = 0;
    }

    __shared__ float s_wk[DD*DD];
    __shared__ float s_wv[DD*DD];
    __shared__ float s_cb[16*DD];
    for (int i = tid; i < DD*DD; i += 256) {
        s_wk[i] = wk[h*DD*DD + i];
        s_wv[i] = wv[h*DD*DD + i];
    }
    for (int i = tid; i < 16*DD; i += 256)
        s_cb[i] = cb[(size_t)h*CC*DD + (size_t)c0*DD + i];
    __syncthreads();
    int d  = tid & 63;
    int cl = tid >> 6;
    for (int cc = cl; cc < 16; cc += 4) {
        float ak = 0.f, av = 0.f;
        #pragma unroll
        for (int e = 0; e < DD; e++) {
            float cbe = s_cb[cc*DD + e];
            ak = fmaf(cbe, s_wk[e*DD + d], ak);
            av = fmaf(cbe, s_wv[e*DD + d], av);
        }
        size_t off = ((size_t)h*CC + (c0 + cc))*DD + d;
        g_k[off]   = ak;
        g_ktf[off] = tf32r(ak);
        g_v[off]   = av;
    }
}

// ---------------------------------------------------------------------------
// Phase B: TF32 mma logits + top-2 tracking.
// grid (BN/128, HH), block 128 (4 warps). Warp owns 32 tokens (2 M-tiles).
// 64-code chunks double-buffered via cp.async.
// ---------------------------------------------------------------------------
__global__ void __launch_bounds__(128)
mma_argmax_kernel(const float* __restrict__ x) {
    int h    = blockIdx.y;
    int tblk = blockIdx.x * 128;
    int tid  = threadIdx.x, warp = tid >> 5, lane = tid & 31;
    int g    = lane >> 2,   tg   = lane & 3;

    __shared__ float k_s[2][CH * 68];

    uint32_t a[2][8][4];
    {
        int r0 = tblk + warp*32 + g;
        const float* xb = x + (size_t)r0 * (HH*DD) + h*DD;
        #pragma unroll
        for (int m = 0; m < 2; m++) {
            #pragma unroll
            for (int ks = 0; ks < 8; ks++) {
                const float* p0 = xb + (size_t)(m*16    ) * (HH*DD) + ks*8 + tg;
                const float* p1 = xb + (size_t)(m*16 + 8) * (HH*DD) + ks*8 + tg;
                a[m][ks][0] = __float_as_uint(tf32r(p0[0] * 0.125f));
                a[m][ks][1] = __float_as_uint(tf32r(p1[0] * 0.125f));
                a[m][ks][2] = __float_as_uint(tf32r(p0[4] * 0.125f));
                a[m][ks][3] = __float_as_uint(tf32r(p1[4] * 0.125f));
            }
        }
    }

    float best[4], sec[4]; int bidx[4];
    #pragma unroll
    for (int s = 0; s < 4; s++) { best[s] = -INFINITY; sec[s] = -INFINITY; bidx[s] = 0; }

    const float* kbase = g_ktf + (size_t)h*CC*DD;

    {
        for (int i = tid; i < CH*16; i += 128) {
            int row = i >> 4, c4 = (i & 15) * 4;
            cpasync16(smem_u32(&k_s[0][row*68 + c4]), kbase + row*DD + c4);
        }
        cpasync_commit();
    }

    for (int c = 0; c < CC/CH; c++) {
        int cur = c & 1;
        if (c + 1 < CC/CH) {
            int nxt = (c + 1) & 1;
            const float* kc = kbase + (size_t)(c + 1)*CH*DD;
            for (int i = tid; i < CH*16; i += 128) {
                int row = i >> 4, c4 = (i & 15) * 4;
                cpasync16(smem_u32(&k_s[nxt][row*68 + c4]), kc + row*DD + c4);
            }
            cpasync_commit();
            cpasync_wait<1>();
        } else {
            cpasync_wait<0>();
        }
        __syncthreads();

        int jt = c * CH;
        #pragma unroll 1
        for (int nt = 0; nt < CH/8; nt++) {
            float c0[4] = {0,0,0,0}, c1[4] = {0,0,0,0};
            const float* kb = &k_s[cur][(nt*8 + g)*68];
            #pragma unroll
            for (int ks = 0; ks < 8; ks++) {
                uint32_t v0 = __float_as_uint(kb[ks*8 + tg]);
                uint32_t v1 = __float_as_uint(kb[ks*8 + tg + 4]);
                mma_tf32(c0, a[0][ks], v0, v1);
                mma_tf32(c1, a[1][ks], v0, v1);
            }
            int code0 = jt + nt*8 + 2*tg;
            upd2(best[0], sec[0], bidx[0], c0[0], c0[1], code0);
            upd2(best[1], sec[1], bidx[1], c0[2], c0[3], code0);
            upd2(best[2], sec[2], bidx[2], c1[0], c1[1], code0);
            upd2(best[3], sec[3], bidx[3], c1[2], c1[3], code0);
        }
        __syncthreads();
    }

    #pragma unroll
    for (int off = 1; off < 4; off <<= 1) {
        #pragma unroll
        for (int s = 0; s < 4; s++) {
            float ob = __shfl_xor_sync(0xffffffffu, best[s], off);
            float os = __shfl_xor_sync(0xffffffffu, sec[s],  off);
            int   oi = __shfl_xor_sync(0xffffffffu, bidx[s], off);
            float ns = fmaxf(fmaxf(sec[s], os), fminf(best[s], ob));
            bool take = (ob > best[s]) || (ob == best[s] && oi < bidx[s]);
            if (take) { best[s] = ob; bidx[s] = oi; }
            sec[s] = ns;
        }
    }

    if (tg == 0) {
        #pragma unroll
        for (int s = 0; s < 4; s++) {
            int m = s >> 1, r8 = (s & 1) * 8;
            int tok = tblk + warp*32 + m*16 + g + r8;
            int e = h*BN + tok;
            if (best[s] - sec[s] < TAU) {
                g_idx[e] = bidx[s] | 0x10000;     // flagged
                g_fixkey[e] = 0ull;
                int pos = atomicAdd(&g_cnt_h[h], 1);
                g_list_h[h][pos] = tok;
            } else {
                g_idx[e] = bidx[s];
            }
        }
    }
}

// ---------------------------------------------------------------------------
// Phase B2: exact fp32 rescue — grid (H, BN/FTOK, FSPLIT), block 512.
// 16 threads per token; each z-block covers CC/FSPLIT codes (2 chunks of 128).
// Partial argmaxes merged via atomicMax on (ordf(score), 1023-code) key.
// Exact 4-way accumulation order.
// ---------------------------------------------------------------------------
__global__ void __launch_bounds__(512)
fix_kernel(const float* __restrict__ x) {
    int h    = blockIdx.x;
    int base = blockIdx.y * FTOK;
    int zc   = blockIdx.z;
    int cnt  = g_cnt_h[h];
    if (base >= cnt) return;

    int tid   = threadIdx.x;
    int tslot = tid >> 4, part = tid & 15;   // 32 tokens x 16 parts
    int ntok  = cnt - base; if (ntok > FTOK) ntok = FTOK;
    bool act  = (tslot < ntok);
    int tok   = g_list_h[h][base + (act ? tslot : 0)];

    float q[64];
    {
        const float4* xq = (const float4*)(x + (size_t)tok*(HH*DD) + h*DD);
        #pragma unroll
        for (int i = 0; i < 16; i++) {
            float4 v = xq[i];
            q[4*i]   = v.x * 0.125f; q[4*i+1] = v.y * 0.125f;
            q[4*i+2] = v.z * 0.125f; q[4*i+3] = v.w * 0.125f;
        }
    }

    __shared__ float ks[128 * 68];

    float best = -INFINITY; int bi = 0;

    for (int c = 0; c < CC/(128*FSPLIT); c++) {
        int jt = (zc * (CC/FSPLIT)) + c * 128;
        __syncthreads();
        for (int i = tid; i < 128*16; i += 512) {
            int row = i >> 4, c4 = (i & 15) * 4;
            float4 v = *(const float4*)(g_k + ((size_t)h*CC + jt + row)*DD + c4);
            *(float4*)&ks[row*68 + c4] = v;
        }
        __syncthreads();

        #pragma unroll 2
        for (int cc8 = 0; cc8 < 8; cc8++) {
            int cl = cc8*16 + part;
            const float4* kr = (const float4*)&ks[cl*68];
            float a0=0.f, a1=0.f, a2=0.f, a3=0.f;
            #pragma unroll
            for (int d4 = 0; d4 < 16; d4++) {
                float4 kv = kr[d4];
                a0 = fmaf(q[4*d4+0], kv.x, a0);
                a1 = fmaf(q[4*d4+1], kv.y, a1);
                a2 = fmaf(q[4*d4+2], kv.z, a2);
                a3 = fmaf(q[4*d4+3], kv.w, a3);
            }
            float acc = (a0 + a1) + (a2 + a3);
            int code = jt + cl;
            if (acc > best) { best = acc; bi = code; }
        }
    }

    if (act) {
        u64 key = ((u64)ordf(best) << 32) | (u64)(uint32_t)(1023 - bi);
        atomicMax(&g_fixkey[h*BN + tok], key);
    }
}

// ---------------------------------------------------------------------------
// Phase C: gather v rows, write indices, histogram. 8 threads per (t,h).
// Flagged tokens decode the exact argmax from g_fixkey.
// ---------------------------------------------------------------------------
__global__ void __launch_bounds__(256)
gather_kernel(float* __restrict__ out_base) {
    int gid = blockIdx.x * 256 + threadIdx.x;
    int s = gid & 7;
    int h = (gid >> 3) & 15;
    int t = gid >> 7;
    int e = h*BN + t;
    int raw = g_idx[e];
    int idx;
    if (raw & 0x10000) idx = 1023 - (int)(g_fixkey[e] & 0xFFFFu);
    else               idx = raw & 1023;
    const float4* vr = (const float4*)(g_v + ((size_t)h*CC + idx)*DD + s*8);
    float4* orow = (float4*)(out_base + (size_t)t*(HH*DD) + h*DD + s*8);
    orow[0] = vr[0]; orow[1] = vr[1];
    if (s == 0) {
        int b  = t >> 12;
        int ii = t & (NN - 1);
        float* idx_out = out_base + (size_t)BN*HH*DD;
        idx_out[((size_t)b*HH + h)*NN + ii] = (float)idx;
        atomicAdd(&g_hist[h*CC + idx], 1);
    }
}

// ---------------------------------------------------------------------------
// Phase D: perplexity per head.
// ---------------------------------------------------------------------------
__global__ void perp_kernel(float* __restrict__ out_base) {
    int h = blockIdx.x;
    __shared__ float red[256];
    float s = 0.f;
    const float inv = 1.0f / (float)BN;
    for (int c = threadIdx.x; c < CC; c += 256) {
        float m = (float)g_hist[h*CC + c] * inv;
        s += m * logf(m + 1e-10f);
    }
    red[threadIdx.x] = s;
    __syncthreads();
    for (int o = 128; o > 0; o >>= 1) {
        if (threadIdx.x < o) red[threadIdx.x] += red[threadIdx.x + o];
        __syncthreads();
    }
    if (threadIdx.x == 0) {
        size_t perp_off = (size_t)BN*HH*DD + (size_t)BB*HH*NN;
        out_base[perp_off + h] = expf(-red[0]);
    }
}

// ---------------------------------------------------------------------------
extern "C" void kernel_launch(void* const* d_in, const int* in_sizes, int n_in,
                              void* d_out, int out_size) {
    const float* x  = (const float*)d_in[0];   // (B, N, H*D)
    const float* cb = (const float*)d_in[1];   // (H, C, D)
    const float* wk = (const float*)d_in[2];   // (H, D, D)
    const float* wv = (const float*)d_in[3];   // (H, D, D)
    float* out = (float*)d_out;

    dim3 gkv(HH, CC/16);
    kv_kernel<<<gkv, 256>>>(cb, wk, wv);

    dim3 gm(BN/128, HH);
    mma_argmax_kernel<<<gm, 128>>>(x);

    dim3 gf(HH, BN/FTOK, FSPLIT);              // blocks past cnt exit instantly
    fix_kernel<<<gf, 512>>>(x);

    gather_kernel<<<(BN*HH*8)/256, 256>>>(out);

    perp_kernel<<<HH, 256>>>(out);
}

// round 16
// speedup vs baseline: 1.0991x; 1.0946x over previous
#include <cuda_runtime.h>
#include <math.h>
#include <stdint.h>

#define BB 2
#define NN 4096
#define HH 16
#define DD 64
#define CC 1024
#define BN (BB*NN)            // 8192 tokens
#define TAU 0.006f
#define FTOK 32               // flagged tokens per fix work item
#define CH 64                 // codes per mma chunk (double-buffered)
#define FSPLIT 4              // code-range splits in fix kernel
#define FIXBLOCKS 256

typedef unsigned long long u64;

// Scratch (no cudaMalloc allowed).
__device__ __align__(16) float g_k  [HH*CC*DD];   // exact projected keys
__device__ __align__(16) float g_ktf[HH*CC*DD];   // tf32-rounded keys
__device__ __align__(16) float g_v  [HH*CC*DD];   // projected values
__device__ int g_hist[HH*CC];
__device__ int g_idx[HH*BN];                      // argmax; bit16 = flagged
__device__ u64 g_fixkey[HH*BN];                   // merged exact (score, code) key
__device__ int g_cnt_h[HH];
__device__ int g_list_h[HH][BN];                  // flagged tokens per head

__device__ __forceinline__ float tf32r(float f) {
    asm("cvt.rna.tf32.f32 %0, %1;" : "=f"(f) : "f"(f));
    return f;
}

__device__ __forceinline__ void mma_tf32(float c[4], const uint32_t a[4],
                                         uint32_t b0, uint32_t b1) {
    asm volatile(
        "mma.sync.aligned.m16n8k8.row.col.f32.tf32.tf32.f32 "
        "{%0,%1,%2,%3}, {%4,%5,%6,%7}, {%8,%9}, {%0,%1,%2,%3};"
        : "+f"(c[0]), "+f"(c[1]), "+f"(c[2]), "+f"(c[3])
        : "r"(a[0]), "r"(a[1]), "r"(a[2]), "r"(a[3]), "r"(b0), "r"(b1));
}

__device__ __forceinline__ uint32_t smem_u32(const void* p) {
    return (uint32_t)__cvta_generic_to_shared(p);
}
__device__ __forceinline__ void cpasync16(uint32_t dst, const void* src) {
    asm volatile("cp.async.cg.shared.global [%0], [%1], 16;"
                 :: "r"(dst), "l"(src));
}
__device__ __forceinline__ void cpasync_commit() {
    asm volatile("cp.async.commit_group;");
}
template<int N>
__device__ __forceinline__ void cpasync_wait() {
    asm volatile("cp.async.wait_group %0;" :: "n"(N));
}

// Order-preserving float -> u32 (monotone: a > b  <=>  enc(a) > enc(b)).
__device__ __forceinline__ uint32_t ordf(float f) {
    uint32_t b = __float_as_uint(f);
    return (b & 0x80000000u) ? ~b : (b | 0x80000000u);
}

// Pairwise top-2 update: two adjacent codes (code0, code0+1), first-max ties.
__device__ __forceinline__ void upd2(float& b, float& s, int& bi,
                                     float v0, float v1, int code0) {
    float mx = fmaxf(v0, v1);
    float mn = fminf(v0, v1);
    int idx  = code0 + ((v1 > v0) ? 1 : 0);
    if (mx > b) { s = fmaxf(b, mn); b = mx; bi = idx; }
    else        { s = fmaxf(s, mx); }
}

// ---------------------------------------------------------------------------
// Phase A: k = cb @ wk (exact + tf32 copy), v = cb @ wv.
// Block (0,0) also zeroes hist/counters (consumed only by later kernels).
// ---------------------------------------------------------------------------
__global__ void kv_kernel(const float* __restrict__ cb,
                          const float* __restrict__ wk,
                          const float* __restrict__ wv) {
    int h  = blockIdx.x;
    int c0 = blockIdx.y * 16;
    int tid = threadIdx.x;

    if (blockIdx.x == 0 && blockIdx.y == 0) {
        for (int i = tid; i < HH*CC; i += 256) g_hist[i] = 0;
        if (tid < HH) g_cnt_h[tid] = 0;
    }

    __shared__ float s_wk[DD*DD];
    __shared__ float s_wv[DD*DD];
    __shared__ float s_cb[16*DD];
    for (int i = tid; i < DD*DD; i += 256) {
        s_wk[i] = wk[h*DD*DD + i];
        s_wv[i] = wv[h*DD*DD + i];
    }
    for (int i = tid; i < 16*DD; i += 256)
        s_cb[i] = cb[(size_t)h*CC*DD + (size_t)c0*DD + i];
    __syncthreads();
    int d  = tid & 63;
    int cl = tid >> 6;
    for (int cc = cl; cc < 16; cc += 4) {
        float ak = 0.f, av = 0.f;
        #pragma unroll
        for (int e = 0; e < DD; e++) {
            float cbe = s_cb[cc*DD + e];
            ak = fmaf(cbe, s_wk[e*DD + d], ak);
            av = fmaf(cbe, s_wv[e*DD + d], av);
        }
        size_t off = ((size_t)h*CC + (c0 + cc))*DD + d;
        g_k[off]   = ak;
        g_ktf[off] = tf32r(ak);
        g_v[off]   = av;
    }
}

// ---------------------------------------------------------------------------
// Phase B: TF32 mma logits + top-2 tracking.
// grid (BN/128, HH), block 128 (4 warps). Warp owns 32 tokens (2 M-tiles).
// 64-code chunks double-buffered via cp.async. 2 N-tiles processed together
// (4 independent HMMA accumulator chains for latency hiding).
// ---------------------------------------------------------------------------
__global__ void __launch_bounds__(128)
mma_argmax_kernel(const float* __restrict__ x) {
    int h    = blockIdx.y;
    int tblk = blockIdx.x * 128;
    int tid  = threadIdx.x, warp = tid >> 5, lane = tid & 31;
    int g    = lane >> 2,   tg   = lane & 3;

    __shared__ float k_s[2][CH * 68];

    uint32_t a[2][8][4];
    {
        int r0 = tblk + warp*32 + g;
        const float* xb = x + (size_t)r0 * (HH*DD) + h*DD;
        #pragma unroll
        for (int m = 0; m < 2; m++) {
            #pragma unroll
            for (int ks = 0; ks < 8; ks++) {
                const float* p0 = xb + (size_t)(m*16    ) * (HH*DD) + ks*8 + tg;
                const float* p1 = xb + (size_t)(m*16 + 8) * (HH*DD) + ks*8 + tg;
                a[m][ks][0] = __float_as_uint(tf32r(p0[0] * 0.125f));
                a[m][ks][1] = __float_as_uint(tf32r(p1[0] * 0.125f));
                a[m][ks][2] = __float_as_uint(tf32r(p0[4] * 0.125f));
                a[m][ks][3] = __float_as_uint(tf32r(p1[4] * 0.125f));
            }
        }
    }

    float best[4], sec[4]; int bidx[4];
    #pragma unroll
    for (int s = 0; s < 4; s++) { best[s] = -INFINITY; sec[s] = -INFINITY; bidx[s] = 0; }

    const float* kbase = g_ktf + (size_t)h*CC*DD;

    {
        for (int i = tid; i < CH*16; i += 128) {
            int row = i >> 4, c4 = (i & 15) * 4;
            cpasync16(smem_u32(&k_s[0][row*68 + c4]), kbase + row*DD + c4);
        }
        cpasync_commit();
    }

    for (int c = 0; c < CC/CH; c++) {
        int cur = c & 1;
        if (c + 1 < CC/CH) {
            int nxt = (c + 1) & 1;
            const float* kc = kbase + (size_t)(c + 1)*CH*DD;
            for (int i = tid; i < CH*16; i += 128) {
                int row = i >> 4, c4 = (i & 15) * 4;
                cpasync16(smem_u32(&k_s[nxt][row*68 + c4]), kc + row*DD + c4);
            }
            cpasync_commit();
            cpasync_wait<1>();
        } else {
            cpasync_wait<0>();
        }
        __syncthreads();

        int jt = c * CH;
        #pragma unroll 1
        for (int nt = 0; nt < CH/8; nt += 2) {
            float c0a[4] = {0,0,0,0}, c1a[4] = {0,0,0,0};
            float c0b[4] = {0,0,0,0}, c1b[4] = {0,0,0,0};
            const float* kba = &k_s[cur][((nt  )*8 + g)*68];
            const float* kbb = &k_s[cur][((nt+1)*8 + g)*68];
            #pragma unroll
            for (int ks = 0; ks < 8; ks++) {
                uint32_t va0 = __float_as_uint(kba[ks*8 + tg]);
                uint32_t va1 = __float_as_uint(kba[ks*8 + tg + 4]);
                uint32_t vb0 = __float_as_uint(kbb[ks*8 + tg]);
                uint32_t vb1 = __float_as_uint(kbb[ks*8 + tg + 4]);
                mma_tf32(c0a, a[0][ks], va0, va1);
                mma_tf32(c1a, a[1][ks], va0, va1);
                mma_tf32(c0b, a[0][ks], vb0, vb1);
                mma_tf32(c1b, a[1][ks], vb0, vb1);
            }
            int codeA = jt + nt*8 + 2*tg;
            int codeB = codeA + 8;
            upd2(best[0], sec[0], bidx[0], c0a[0], c0a[1], codeA);
            upd2(best[1], sec[1], bidx[1], c0a[2], c0a[3], codeA);
            upd2(best[2], sec[2], bidx[2], c1a[0], c1a[1], codeA);
            upd2(best[3], sec[3], bidx[3], c1a[2], c1a[3], codeA);
            upd2(best[0], sec[0], bidx[0], c0b[0], c0b[1], codeB);
            upd2(best[1], sec[1], bidx[1], c0b[2], c0b[3], codeB);
            upd2(best[2], sec[2], bidx[2], c1b[0], c1b[1], codeB);
            upd2(best[3], sec[3], bidx[3], c1b[2], c1b[3], codeB);
        }
        __syncthreads();
    }

    #pragma unroll
    for (int off = 1; off < 4; off <<= 1) {
        #pragma unroll
        for (int s = 0; s < 4; s++) {
            float ob = __shfl_xor_sync(0xffffffffu, best[s], off);
            float os = __shfl_xor_sync(0xffffffffu, sec[s],  off);
            int   oi = __shfl_xor_sync(0xffffffffu, bidx[s], off);
            float ns = fmaxf(fmaxf(sec[s], os), fminf(best[s], ob));
            bool take = (ob > best[s]) || (ob == best[s] && oi < bidx[s]);
            if (take) { best[s] = ob; bidx[s] = oi; }
            sec[s] = ns;
        }
    }

    if (tg == 0) {
        #pragma unroll
        for (int s = 0; s < 4; s++) {
            int m = s >> 1, r8 = (s & 1) * 8;
            int tok = tblk + warp*32 + m*16 + g + r8;
            int e = h*BN + tok;
            if (best[s] - sec[s] < TAU) {
                g_idx[e] = bidx[s] | 0x10000;     // flagged
                g_fixkey[e] = 0ull;
                int pos = atomicAdd(&g_cnt_h[h], 1);
                g_list_h[h][pos] = tok;
            } else {
                g_idx[e] = bidx[s];
            }
        }
    }
}

// ---------------------------------------------------------------------------
// Phase B2: exact fp32 rescue — FIXBLOCKS persistent blocks grid-striding the
// (grp, z, h) work space; empty items are a 1-load skip (no CTA sweep).
// 16 threads per token; each z-item covers CC/FSPLIT codes.
// Partial argmaxes merged via atomicMax on (ordf(score), 1023-code) key.
// Exact 4-way accumulation order. cnt is uniform per block per item, so the
// `continue` and inner __syncthreads are convergence-safe.
// ---------------------------------------------------------------------------
__global__ void __launch_bounds__(512)
fix_kernel(const float* __restrict__ x) {
    __shared__ float ks[128 * 68];

    int tid   = threadIdx.x;
    int tslot = tid >> 4, part = tid & 15;   // 32 tokens x 16 parts

    const int NWI = (BN/FTOK) * FSPLIT * HH; // grp-major, then z, then h

    for (int wi = blockIdx.x; wi < NWI; wi += FIXBLOCKS) {
        int h    = wi & (HH - 1);
        int rest = wi >> 4;
        int zc   = rest & (FSPLIT - 1);
        int grp  = rest >> 2;                // FSPLIT == 4
        int cnt  = g_cnt_h[h];
        int base = grp * FTOK;
        if (base >= cnt) continue;

        int ntok = cnt - base; if (ntok > FTOK) ntok = FTOK;
        bool act = (tslot < ntok);
        int tok  = g_list_h[h][base + (act ? tslot : 0)];

        float q[64];
        {
            const float4* xq = (const float4*)(x + (size_t)tok*(HH*DD) + h*DD);
            #pragma unroll
            for (int i = 0; i < 16; i++) {
                float4 v = xq[i];
                q[4*i]   = v.x * 0.125f; q[4*i+1] = v.y * 0.125f;
                q[4*i+2] = v.z * 0.125f; q[4*i+3] = v.w * 0.125f;
            }
        }

        float best = -INFINITY; int bi = 0;

        for (int c = 0; c < CC/(128*FSPLIT); c++) {
            int jt = (zc * (CC/FSPLIT)) + c * 128;
            __syncthreads();
            for (int i = tid; i < 128*16; i += 512) {
                int row = i >> 4, c4 = (i & 15) * 4;
                float4 v = *(const float4*)(g_k + ((size_t)h*CC + jt + row)*DD + c4);
                *(float4*)&ks[row*68 + c4] = v;
            }
            __syncthreads();

            #pragma unroll 2
            for (int cc8 = 0; cc8 < 8; cc8++) {
                int cl = cc8*16 + part;
                const float4* kr = (const float4*)&ks[cl*68];
                float a0=0.f, a1=0.f, a2=0.f, a3=0.f;
                #pragma unroll
                for (int d4 = 0; d4 < 16; d4++) {
                    float4 kv = kr[d4];
                    a0 = fmaf(q[4*d4+0], kv.x, a0);
                    a1 = fmaf(q[4*d4+1], kv.y, a1);
                    a2 = fmaf(q[4*d4+2], kv.z, a2);
                    a3 = fmaf(q[4*d4+3], kv.w, a3);
                }
                float acc = (a0 + a1) + (a2 + a3);
                int code = jt + cl;
                if (acc > best) { best = acc; bi = code; }
            }
        }

        if (act) {
            u64 key = ((u64)ordf(best) << 32) | (u64)(uint32_t)(1023 - bi);
            atomicMax(&g_fixkey[h*BN + tok], key);
        }
        __syncthreads();   // ks reuse barrier before next work item
    }
}

// ---------------------------------------------------------------------------
// Phase C: gather v rows, write indices, histogram. 8 threads per (t,h).
// Flagged tokens decode the exact argmax from g_fixkey.
// ---------------------------------------------------------------------------
__global__ void __launch_bounds__(256)
gather_kernel(float* __restrict__ out_base) {
    int gid = blockIdx.x * 256 + threadIdx.x;
    int s = gid & 7;
    int h = (gid >> 3) & 15;
    int t = gid >> 7;
    int e = h*BN + t;
    int raw = g_idx[e];
    int idx;
    if (raw & 0x10000) idx = 1023 - (int)(g_fixkey[e] & 0xFFFFu);
    else               idx = raw & 1023;
    const float4* vr = (const float4*)(g_v + ((size_t)h*CC + idx)*DD + s*8);
    float4* orow = (float4*)(out_base + (size_t)t*(HH*DD) + h*DD + s*8);
    orow[0] = vr[0]; orow[1] = vr[1];
    if (s == 0) {
        int b  = t >> 12;
        int ii = t & (NN - 1);
        float* idx_out = out_base + (size_t)BN*HH*DD;
        idx_out[((size_t)b*HH + h)*NN + ii] = (float)idx;
        atomicAdd(&g_hist[h*CC + idx], 1);
    }
}

// ---------------------------------------------------------------------------
// Phase D: perplexity per head.
// ---------------------------------------------------------------------------
__global__ void perp_kernel(float* __restrict__ out_base) {
    int h = blockIdx.x;
    __shared__ float red[256];
    float s = 0.f;
    const float inv = 1.0f / (float)BN;
    for (int c = threadIdx.x; c < CC; c += 256) {
        float m = (float)g_hist[h*CC + c] * inv;
        s += m * logf(m + 1e-10f);
    }
    red[threadIdx.x] = s;
    __syncthreads();
    for (int o = 128; o > 0; o >>= 1) {
        if (threadIdx.x < o) red[threadIdx.x] += red[threadIdx.x + o];
        __syncthreads();
    }
    if (threadIdx.x == 0) {
        size_t perp_off = (size_t)BN*HH*DD + (size_t)BB*HH*NN;
        out_base[perp_off + h] = expf(-red[0]);
    }
}

// ---------------------------------------------------------------------------
extern "C" void kernel_launch(void* const* d_in, const int* in_sizes, int n_in,
                              void* d_out, int out_size) {
    const float* x  = (const float*)d_in[0];   // (B, N, H*D)
    const float* cb = (const float*)d_in[1];   // (H, C, D)
    const float* wk = (const float*)d_in[2];   // (H, D, D)
    const float* wv = (const float*)d_in[3];   // (H, D, D)
    float* out = (float*)d_out;

    dim3 gkv(HH, CC/16);
    kv_kernel<<<gkv, 256>>>(cb, wk, wv);

    dim3 gm(BN/128, HH);
    mma_argmax_kernel<<<gm, 128>>>(x);

    fix_kernel<<<FIXBLOCKS, 512>>>(x);

    gather_kernel<<<(BN*HH*8)/256, 256>>>(out);

    perp_kernel<<<HH, 256>>>(out);
}